// round 7
// baseline (speedup 1.0000x reference)
#include <cuda_runtime.h>
#include <cstdint>

typedef unsigned long long u64t;

#define T_STEPS 8192
#define DIM     2048
#define R_CTAS  128
#define R_THR   512   // 16 warps

// ---------------- scratch (no allocations allowed) ----------------
__device__ float g_pre[(size_t)T_STEPS * DIM];          // 64 MB
// h ping-pong: ONE u64 per element = {lo32: f32 value bits, hi32: step tag}.
// Accessed ONLY with morally-strong gpu-scope ops (release store / acquire
// load): strong 8B accesses are single-copy atomic and coherent. Weak .cg
// accesses here were a formal data race (undefined read values) — that was
// the R5/R6 bug.
__device__ __align__(16) u64t g_hp[2][DIM];

// ---------------- f32x2 helpers (sm_100+ packed fp32) ----------------
__device__ __forceinline__ u64t fma2(u64t a, u64t b, u64t c) {
    u64t d;
    asm("fma.rn.f32x2 %0, %1, %2, %3;" : "=l"(d) : "l"(a), "l"(b), "l"(c));
    return d;
}
__device__ __forceinline__ u64t add2(u64t a, u64t b) {
    u64t d;
    asm("add.rn.f32x2 %0, %1, %2;" : "=l"(d) : "l"(a), "l"(b));
    return d;
}
__device__ __forceinline__ u64t pk2(float lo, float hi) {
    u64t r;
    asm("mov.b64 %0, {%1, %2};" : "=l"(r) : "f"(lo), "f"(hi));
    return r;
}
__device__ __forceinline__ float sum2(u64t v) {
    float a, b;
    asm("mov.b64 {%0, %1}, %2;" : "=f"(a), "=f"(b) : "l"(v));
    return a + b;
}

// ---- morally-strong gpu-scope slot accesses (the sync carriers) ----
__device__ __forceinline__ u64t ldacq_u64(const u64t* p) {
    u64t r;
    asm volatile("ld.acquire.gpu.global.u64 %0, [%1];"
                 : "=l"(r) : "l"(p) : "memory");
    return r;
}
__device__ __forceinline__ void strel_u64(u64t* p, u64t v) {
    asm volatile("st.release.gpu.global.u64 [%0], %1;"
                 :: "l"(p), "l"(v) : "memory");
}
// plain L2 load for pre-computed data (no race: written by earlier kernel)
__device__ __forceinline__ float ldcg_f32(const float* p) {
    float r;
    asm volatile("ld.global.cg.f32 %0, [%1];" : "=f"(r) : "l"(p));
    return r;
}

// ---------------- init: seed h0 with tag 0, poison other buffer ----------
__global__ void init_kernel(const float* __restrict__ h0) {
    int i = blockIdx.x * blockDim.x + threadIdx.x;
    if (i < DIM) {
        g_hp[0][i] = (u64t)__float_as_uint(h0[i]);      // tag 0 in hi32
        g_hp[1][i] = 0xFFFFFFFF00000000ull;             // poison tag
    }
}

// ---------------- pre-GEMM: pre = x @ W1^T + b1 ----------------
#define BM 128
#define BN 128
#define BK 16

__global__ void __launch_bounds__(256, 2)
gemm_pre_kernel(const float* __restrict__ X, const float* __restrict__ W1,
                const float* __restrict__ b1) {
    __shared__ u64t  Xd[BK * BM];     // 16 KB, duplicated floats
    __shared__ float Ws[BK * BN];     // 8 KB

    const int tid = threadIdx.x;
    const int tx = tid & 15;          // N direction (16)
    const int ty = tid >> 4;          // M direction (16)
    const int m0 = blockIdx.y * BM;
    const int n0 = blockIdx.x * BN;

    u64t acc[8][4];
#pragma unroll
    for (int i = 0; i < 8; i++)
#pragma unroll
        for (int j = 0; j < 4; j++) acc[i][j] = 0ull;

    for (int kt = 0; kt < DIM; kt += BK) {
        __syncthreads();
#pragma unroll
        for (int h = 0; h < 2; h++) {
            int idx = tid + h * 256;
            int k4  = idx & 3;
            int r   = idx >> 2;
            float4 xv = *(const float4*)(X + (size_t)(m0 + r) * DIM + kt + k4 * 4);
            Xd[(k4 * 4 + 0) * BM + r] = pk2(xv.x, xv.x);
            Xd[(k4 * 4 + 1) * BM + r] = pk2(xv.y, xv.y);
            Xd[(k4 * 4 + 2) * BM + r] = pk2(xv.z, xv.z);
            Xd[(k4 * 4 + 3) * BM + r] = pk2(xv.w, xv.w);
            float4 wv = *(const float4*)(W1 + (size_t)(n0 + r) * DIM + kt + k4 * 4);
            Ws[(k4 * 4 + 0) * BN + r] = wv.x;
            Ws[(k4 * 4 + 1) * BN + r] = wv.y;
            Ws[(k4 * 4 + 2) * BN + r] = wv.z;
            Ws[(k4 * 4 + 3) * BN + r] = wv.w;
        }
        __syncthreads();

#pragma unroll
        for (int k = 0; k < BK; k++) {
            const u64t*  Xk = Xd + k * BM;
            const float* Wk = Ws + k * BN;
            u64t a[8];
            {
                ulonglong2 a0 = *(const ulonglong2*)(Xk + ty * 4);
                ulonglong2 a1 = *(const ulonglong2*)(Xk + ty * 4 + 2);
                ulonglong2 a2 = *(const ulonglong2*)(Xk + 64 + ty * 4);
                ulonglong2 a3 = *(const ulonglong2*)(Xk + 64 + ty * 4 + 2);
                a[0] = a0.x; a[1] = a0.y; a[2] = a1.x; a[3] = a1.y;
                a[4] = a2.x; a[5] = a2.y; a[6] = a3.x; a[7] = a3.y;
            }
            u64t bb[4];
            {
                ulonglong2 b0 = *(const ulonglong2*)(Wk + tx * 4);
                ulonglong2 b1v = *(const ulonglong2*)(Wk + 64 + tx * 4);
                bb[0] = b0.x; bb[1] = b0.y; bb[2] = b1v.x; bb[3] = b1v.y;
            }
#pragma unroll
            for (int i = 0; i < 8; i++)
#pragma unroll
                for (int j = 0; j < 4; j++)
                    acc[i][j] = fma2(a[i], bb[j], acc[i][j]);
        }
    }

#pragma unroll
    for (int j = 0; j < 4; j++) {
        int col = n0 + ((j >> 1) * 64) + tx * 4 + (j & 1) * 2;
        u64t bp = pk2(b1[col], b1[col + 1]);
#pragma unroll
        for (int i = 0; i < 8; i++) {
            int row = m0 + ((i >> 2) * 64) + ty * 4 + (i & 3);
            u64t v = add2(acc[i][j], bp);
            *(u64t*)(g_pre + (size_t)row * DIM + col) = v;
        }
    }
}

// ---------------- recurrence: tag-signaled ping-pong, NO grid barrier ----
// 128 CTAs x 512 threads, 1 CTA/SM, co-resident (128 < 148 SMs).
// Per step:
//   phase A: 512 threads poll all 2048 packed {tag|value} u64s for tag==t
//            (4 scalar acquire loads each), stage values into smem. bar.
//   phase B: warp w computes 16 partial row dots over its 128 cols from
//            smem (broadcast LDS) with W2 held in REGISTERS; two-level
//            shfl+smem reduce; lane0 release-stores packed {t+1 | relu}.
// Safety: a producer writes tag t+1 only after its CTA observed ALL tags==t
// (acquire loads + bar.sync + release store build the causality chain), so
// every consumer has finished reading the parity buffer being overwritten.
__global__ void __launch_bounds__(R_THR, 1)
recur_kernel(const float* __restrict__ W2, const float* __restrict__ b2) {
    const int tid  = threadIdx.x;
    const int w    = tid >> 5;
    const int l    = tid & 31;
    const int rowl = l & 15;
    const int half = l >> 4;
    const int rbase = blockIdx.x * 16;
    const int cbase = w * 128 + half * 64;

    u64t wreg[32];
    {
        const ulonglong2* wp =
            (const ulonglong2*)(W2 + (size_t)(rbase + rowl) * DIM + cbase);
#pragma unroll
        for (int i = 0; i < 16; i++) {
            ulonglong2 v = wp[i];
            wreg[2 * i]     = v.x;
            wreg[2 * i + 1] = v.y;
        }
    }
    const float b2r = b2[rbase + w];   // lane 0 of warp w owns row rbase+w

    __shared__ float h_s[DIM];         // staged h_t
    __shared__ float part[16 * 17];

    for (int t = 0; t < T_STEPS; t++) {
        const unsigned tg = (unsigned)t;
        const int p = t & 1;

        float prev = 0.f;
        if (l == 0)
            prev = ldcg_f32(&g_pre[(size_t)t * DIM + rbase + w]);

        // ---- phase A: poll 4 packed u64s (acquire), stage to smem ----
        {
            const u64t* pp = g_hp[p] + tid * 4;
            u64t s0, s1, s2, s3;
            do { s0 = ldacq_u64(pp + 0); } while ((unsigned)(s0 >> 32) != tg);
            do { s1 = ldacq_u64(pp + 1); } while ((unsigned)(s1 >> 32) != tg);
            do { s2 = ldacq_u64(pp + 2); } while ((unsigned)(s2 >> 32) != tg);
            do { s3 = ldacq_u64(pp + 3); } while ((unsigned)(s3 >> 32) != tg);
            float4 hv;
            hv.x = __uint_as_float((unsigned)s0);
            hv.y = __uint_as_float((unsigned)s1);
            hv.z = __uint_as_float((unsigned)s2);
            hv.w = __uint_as_float((unsigned)s3);
            *(float4*)(h_s + tid * 4) = hv;
        }
        __syncthreads();

        // ---- phase B: dot from smem (broadcast), W2 in registers ----
        const ulonglong2* hp = (const ulonglong2*)(h_s + cbase);
        u64t a0 = 0ull, a1 = 0ull;
#pragma unroll
        for (int i = 0; i < 16; i++) {
            ulonglong2 hv = hp[i];
            a0 = fma2(wreg[2 * i],     hv.x, a0);
            a1 = fma2(wreg[2 * i + 1], hv.y, a1);
        }
        float s = sum2(a0) + sum2(a1);
        s += __shfl_xor_sync(0xffffffffu, s, 16);
        if (half == 0) part[w * 17 + rowl] = s;
        __syncthreads();

        float v = (l < 16) ? part[l * 17 + w] : 0.f;
        v += __shfl_xor_sync(0xffffffffu, v, 8);
        v += __shfl_xor_sync(0xffffffffu, v, 4);
        v += __shfl_xor_sync(0xffffffffu, v, 2);
        v += __shfl_xor_sync(0xffffffffu, v, 1);
        if (l == 0) {
            float hnew = fmaxf(v + prev + b2r, 0.f);
            u64t pkd = ((u64t)(tg + 1u) << 32) | (u64t)__float_as_uint(hnew);
            strel_u64(&g_hp[p ^ 1][rbase + w], pkd);
        }
        // no barrier: next step's acquire-poll provides all ordering
    }
}

// ---------------- head: out = h @ Wf^T + bf (1x4) ----------------
__global__ void final_kernel(const float* __restrict__ Wf,
                             const float* __restrict__ bf,
                             float* __restrict__ out) {
    const int w = threadIdx.x >> 5, l = threadIdx.x & 31;
    const u64t* h = g_hp[0];                  // 8192 steps -> parity 0
    float s = 0.f;
    for (int d = l; d < DIM; d += 32)
        s += __uint_as_float((unsigned)h[d]) * Wf[(size_t)w * DIM + d];
    s += __shfl_xor_sync(0xffffffffu, s, 16);
    s += __shfl_xor_sync(0xffffffffu, s, 8);
    s += __shfl_xor_sync(0xffffffffu, s, 4);
    s += __shfl_xor_sync(0xffffffffu, s, 2);
    s += __shfl_xor_sync(0xffffffffu, s, 1);
    if (l == 0) out[w] = s + bf[w];
}

extern "C" void kernel_launch(void* const* d_in, const int* in_sizes, int n_in,
                              void* d_out, int out_size) {
    const float* x  = (const float*)d_in[0];
    const float* h0 = (const float*)d_in[1];
    const float* W1 = (const float*)d_in[2];
    const float* b1 = (const float*)d_in[3];
    const float* W2 = (const float*)d_in[4];
    const float* b2 = (const float*)d_in[5];
    const float* Wf = (const float*)d_in[6];
    const float* bf = (const float*)d_in[7];
    float* out = (float*)d_out;

    init_kernel<<<8, 256>>>(h0);
    dim3 gg(DIM / BN, T_STEPS / BM);          // (16, 64)
    gemm_pre_kernel<<<gg, 256>>>(x, W1, b1);
    recur_kernel<<<R_CTAS, R_THR>>>(W2, b2);
    final_kernel<<<1, 128>>>(Wf, bf, out);
}

// round 8
// speedup vs baseline: 1.1504x; 1.1504x over previous
#include <cuda_runtime.h>
#include <cstdint>

typedef unsigned long long u64t;

#define T_STEPS 8192
#define DIM     2048
#define R_CTAS  128
#define R_THR   512   // 16 warps

// ---------------- scratch (no allocations allowed) ----------------
__device__ float g_pre[(size_t)T_STEPS * DIM];          // 64 MB
// h ping-pong value buffers (plain floats; publication ordered via flags)
__device__ __align__(16) float g_hv[2][DIM];
// per-CTA progress counters, one 128B line each; flag[c] == 16*(t+1) means
// CTA c has published all 16 of its h_{t+1} rows.
__device__ u64t g_flag[R_CTAS * 16];

// ---------------- f32x2 helpers (sm_100+ packed fp32) ----------------
__device__ __forceinline__ u64t fma2(u64t a, u64t b, u64t c) {
    u64t d;
    asm("fma.rn.f32x2 %0, %1, %2, %3;" : "=l"(d) : "l"(a), "l"(b), "l"(c));
    return d;
}
__device__ __forceinline__ u64t add2(u64t a, u64t b) {
    u64t d;
    asm("add.rn.f32x2 %0, %1, %2;" : "=l"(d) : "l"(a), "l"(b));
    return d;
}
__device__ __forceinline__ u64t pk2(float lo, float hi) {
    u64t r;
    asm("mov.b64 %0, {%1, %2};" : "=l"(r) : "f"(lo), "f"(hi));
    return r;
}
__device__ __forceinline__ float sum2(u64t v) {
    float a, b;
    asm("mov.b64 {%0, %1}, %2;" : "=f"(a), "=f"(b) : "l"(v));
    return a + b;
}

// ---- sync carriers (morally strong, gpu scope) ----
__device__ __forceinline__ u64t ldacq_u64(const u64t* p) {
    u64t r;
    asm volatile("ld.acquire.gpu.global.u64 %0, [%1];"
                 : "=l"(r) : "l"(p) : "memory");
    return r;
}
__device__ __forceinline__ void red_release_add1(u64t* p) {
    asm volatile("red.release.gpu.global.add.u64 [%0], %1;"
                 :: "l"(p), "l"(1ull) : "memory");
}
__device__ __forceinline__ void strelax_f32(float* p, float v) {
    asm volatile("st.relaxed.gpu.global.f32 [%0], %1;"
                 :: "l"(p), "f"(v) : "memory");
}
// weak L2 loads for payload (ordered by the acquire/release flag chain)
__device__ __forceinline__ float4 ldcg_v4f32(const float4* p) {
    float4 r;
    asm volatile("ld.global.cg.v4.f32 {%0, %1, %2, %3}, [%4];"
                 : "=f"(r.x), "=f"(r.y), "=f"(r.z), "=f"(r.w) : "l"(p));
    return r;
}
__device__ __forceinline__ float ldcg_f32(const float* p) {
    float r;
    asm volatile("ld.global.cg.f32 %0, [%1];" : "=f"(r) : "l"(p));
    return r;
}

// ---------------- init: seed h0, zero flags ----------------
__global__ void init_kernel(const float* __restrict__ h0) {
    int i = blockIdx.x * blockDim.x + threadIdx.x;
    if (i < DIM) g_hv[0][i] = h0[i];
    if (i < R_CTAS * 16) g_flag[i] = 0ull;
}

// ---------------- pre-GEMM: pre = x @ W1^T + b1 ----------------
#define BM 128
#define BN 128
#define BK 16

__global__ void __launch_bounds__(256, 2)
gemm_pre_kernel(const float* __restrict__ X, const float* __restrict__ W1,
                const float* __restrict__ b1) {
    __shared__ u64t  Xd[BK * BM];     // 16 KB, duplicated floats
    __shared__ float Ws[BK * BN];     // 8 KB

    const int tid = threadIdx.x;
    const int tx = tid & 15;          // N direction (16)
    const int ty = tid >> 4;          // M direction (16)
    const int m0 = blockIdx.y * BM;
    const int n0 = blockIdx.x * BN;

    u64t acc[8][4];
#pragma unroll
    for (int i = 0; i < 8; i++)
#pragma unroll
        for (int j = 0; j < 4; j++) acc[i][j] = 0ull;

    for (int kt = 0; kt < DIM; kt += BK) {
        __syncthreads();
#pragma unroll
        for (int h = 0; h < 2; h++) {
            int idx = tid + h * 256;
            int k4  = idx & 3;
            int r   = idx >> 2;
            float4 xv = *(const float4*)(X + (size_t)(m0 + r) * DIM + kt + k4 * 4);
            Xd[(k4 * 4 + 0) * BM + r] = pk2(xv.x, xv.x);
            Xd[(k4 * 4 + 1) * BM + r] = pk2(xv.y, xv.y);
            Xd[(k4 * 4 + 2) * BM + r] = pk2(xv.z, xv.z);
            Xd[(k4 * 4 + 3) * BM + r] = pk2(xv.w, xv.w);
            float4 wv = *(const float4*)(W1 + (size_t)(n0 + r) * DIM + kt + k4 * 4);
            Ws[(k4 * 4 + 0) * BN + r] = wv.x;
            Ws[(k4 * 4 + 1) * BN + r] = wv.y;
            Ws[(k4 * 4 + 2) * BN + r] = wv.z;
            Ws[(k4 * 4 + 3) * BN + r] = wv.w;
        }
        __syncthreads();

#pragma unroll
        for (int k = 0; k < BK; k++) {
            const u64t*  Xk = Xd + k * BM;
            const float* Wk = Ws + k * BN;
            u64t a[8];
            {
                ulonglong2 a0 = *(const ulonglong2*)(Xk + ty * 4);
                ulonglong2 a1 = *(const ulonglong2*)(Xk + ty * 4 + 2);
                ulonglong2 a2 = *(const ulonglong2*)(Xk + 64 + ty * 4);
                ulonglong2 a3 = *(const ulonglong2*)(Xk + 64 + ty * 4 + 2);
                a[0] = a0.x; a[1] = a0.y; a[2] = a1.x; a[3] = a1.y;
                a[4] = a2.x; a[5] = a2.y; a[6] = a3.x; a[7] = a3.y;
            }
            u64t bb[4];
            {
                ulonglong2 b0 = *(const ulonglong2*)(Wk + tx * 4);
                ulonglong2 b1v = *(const ulonglong2*)(Wk + 64 + tx * 4);
                bb[0] = b0.x; bb[1] = b0.y; bb[2] = b1v.x; bb[3] = b1v.y;
            }
#pragma unroll
            for (int i = 0; i < 8; i++)
#pragma unroll
                for (int j = 0; j < 4; j++)
                    acc[i][j] = fma2(a[i], bb[j], acc[i][j]);
        }
    }

#pragma unroll
    for (int j = 0; j < 4; j++) {
        int col = n0 + ((j >> 1) * 64) + tx * 4 + (j & 1) * 2;
        u64t bp = pk2(b1[col], b1[col + 1]);
#pragma unroll
        for (int i = 0; i < 8; i++) {
            int row = m0 + ((i >> 2) * 64) + ty * 4 + (i & 3);
            u64t v = add2(acc[i][j], bp);
            *(u64t*)(g_pre + (size_t)row * DIM + col) = v;
        }
    }
}

// ---------------- recurrence: flag-signaled ping-pong ----------------
// 128 CTAs x 512 threads, 1 CTA/SM, co-resident (128 < 148 SMs).
// Per step t:
//   poll : threads 0..127 each acquire-poll ONE per-CTA flag (parallel,
//          1 L2 round trip, 128 KB/round chip-wide). bar.
//   bulk : 512 threads ld.cg.v4 the 8 KB h_t buffer, stage to smem. bar.
//   comp : warp w = 16 partial row dots over its 128 cols (W2 in regs,
//          f32x2 FMA); two-level shfl+smem reduce.
//   pub  : lane0 st.relaxed h_{t+1}[rbase+w]; red.release flag[cta] += 1.
// Flag[c] >= 16*t  <=>  CTA c published all 16 rows of h_t. The acquire on
// the flag + release on the red orders the relaxed value stores (no
// weak/weak race). Overwrite safety: producer writes buf[p] at step t+1
// only after flag>=16(t+1), which happens-after every CTA's bulk read of
// h_t from buf[p] at step t.
__global__ void __launch_bounds__(R_THR, 1)
recur_kernel(const float* __restrict__ W2, const float* __restrict__ b2) {
    const int tid  = threadIdx.x;
    const int w    = tid >> 5;
    const int l    = tid & 31;
    const int rowl = l & 15;
    const int half = l >> 4;
    const int rbase = blockIdx.x * 16;
    const int cbase = w * 128 + half * 64;

    u64t wreg[32];
    {
        const ulonglong2* wp =
            (const ulonglong2*)(W2 + (size_t)(rbase + rowl) * DIM + cbase);
#pragma unroll
        for (int i = 0; i < 16; i++) {
            ulonglong2 v = wp[i];
            wreg[2 * i]     = v.x;
            wreg[2 * i + 1] = v.y;
        }
    }
    const float b2r = b2[rbase + w];   // lane 0 of warp w owns row rbase+w

    __shared__ float h_s[DIM];         // staged h_t
    __shared__ float part[16 * 17];

    for (int t = 0; t < T_STEPS; t++) {
        const int p = t & 1;

        float prev = 0.f;
        if (l == 0)    // issued before the poll; DRAM latency hidden by it
            prev = ldcg_f32(&g_pre[(size_t)t * DIM + rbase + w]);

        // ---- poll: parallel per-CTA flags ----
        if (tid < R_CTAS) {
            const u64t tgt = (u64t)t * 16u;
            while (ldacq_u64(&g_flag[tid * 16]) < tgt) { }
        }
        __syncthreads();

        // ---- bulk read h_t (weak cg, ordered by the acquire above) ----
        {
            float4 hv = ldcg_v4f32((const float4*)(g_hv[p]) + tid);
            *(float4*)(h_s + tid * 4) = hv;
        }
        __syncthreads();

        // ---- compute: dot from smem (broadcast), W2 in registers ----
        const ulonglong2* hp = (const ulonglong2*)(h_s + cbase);
        u64t a0 = 0ull, a1 = 0ull;
#pragma unroll
        for (int i = 0; i < 16; i++) {
            ulonglong2 hv = hp[i];
            a0 = fma2(wreg[2 * i],     hv.x, a0);
            a1 = fma2(wreg[2 * i + 1], hv.y, a1);
        }
        float s = sum2(a0) + sum2(a1);
        s += __shfl_xor_sync(0xffffffffu, s, 16);
        if (half == 0) part[w * 17 + rowl] = s;
        __syncthreads();

        float v = (l < 16) ? part[l * 17 + w] : 0.f;
        v += __shfl_xor_sync(0xffffffffu, v, 8);
        v += __shfl_xor_sync(0xffffffffu, v, 4);
        v += __shfl_xor_sync(0xffffffffu, v, 2);
        v += __shfl_xor_sync(0xffffffffu, v, 1);
        if (l == 0) {
            float hnew = fmaxf(v + prev + b2r, 0.f);
            strelax_f32(&g_hv[p ^ 1][rbase + w], hnew);
            red_release_add1(&g_flag[blockIdx.x * 16]);
        }
        // no trailing barrier: next step's poll+bars provide all ordering
    }
}

// ---------------- head: out = h @ Wf^T + bf (1x4) ----------------
__global__ void final_kernel(const float* __restrict__ Wf,
                             const float* __restrict__ bf,
                             float* __restrict__ out) {
    const int w = threadIdx.x >> 5, l = threadIdx.x & 31;
    const float* h = g_hv[0];                 // 8192 steps -> parity 0
    float s = 0.f;
    for (int d = l; d < DIM; d += 32)
        s += h[d] * Wf[(size_t)w * DIM + d];
    s += __shfl_xor_sync(0xffffffffu, s, 16);
    s += __shfl_xor_sync(0xffffffffu, s, 8);
    s += __shfl_xor_sync(0xffffffffu, s, 4);
    s += __shfl_xor_sync(0xffffffffu, s, 2);
    s += __shfl_xor_sync(0xffffffffu, s, 1);
    if (l == 0) out[w] = s + bf[w];
}

extern "C" void kernel_launch(void* const* d_in, const int* in_sizes, int n_in,
                              void* d_out, int out_size) {
    const float* x  = (const float*)d_in[0];
    const float* h0 = (const float*)d_in[1];
    const float* W1 = (const float*)d_in[2];
    const float* b1 = (const float*)d_in[3];
    const float* W2 = (const float*)d_in[4];
    const float* b2 = (const float*)d_in[5];
    const float* Wf = (const float*)d_in[6];
    const float* bf = (const float*)d_in[7];
    float* out = (float*)d_out;

    init_kernel<<<8, 256>>>(h0);
    dim3 gg(DIM / BN, T_STEPS / BM);          // (16, 64)
    gemm_pre_kernel<<<gg, 256>>>(x, W1, b1);
    recur_kernel<<<R_CTAS, R_THR>>>(W2, b2);
    final_kernel<<<1, 128>>>(Wf, bf, out);
}

// round 9
// speedup vs baseline: 2.0452x; 1.7778x over previous
#include <cuda_runtime.h>
#include <cstdint>

typedef unsigned long long u64t;

#define T_STEPS 8192
#define DIM     2048
#define R_CTAS  128
#define R_THR   512   // 16 warps

// ---------------- scratch (no allocations allowed) ----------------
__device__ float g_pre[(size_t)T_STEPS * DIM];          // 64 MB
// h ping-pong: ONE u64 slot per element = {hi32: step tag, lo32: f32 bits}.
// All slot accesses are relaxed STRONG gpu-scope ops (atomic + coherent).
// No fences needed: every published value data-depends on ALL consumed
// loads (full W2 coupling), so dataflow enforces the causal chain.
__device__ __align__(16) u64t g_ht[2][DIM];

// ---------------- f32x2 helpers (sm_100+ packed fp32) ----------------
__device__ __forceinline__ u64t fma2(u64t a, u64t b, u64t c) {
    u64t d;
    asm("fma.rn.f32x2 %0, %1, %2, %3;" : "=l"(d) : "l"(a), "l"(b), "l"(c));
    return d;
}
__device__ __forceinline__ u64t add2(u64t a, u64t b) {
    u64t d;
    asm("add.rn.f32x2 %0, %1, %2;" : "=l"(d) : "l"(a), "l"(b));
    return d;
}
__device__ __forceinline__ u64t pk2(float lo, float hi) {
    u64t r;
    asm("mov.b64 %0, {%1, %2};" : "=l"(r) : "f"(lo), "f"(hi));
    return r;
}
__device__ __forceinline__ float sum2(u64t v) {
    float a, b;
    asm("mov.b64 {%0, %1}, %2;" : "=f"(a), "=f"(b) : "l"(v));
    return a + b;
}

// ---- relaxed strong gpu-scope slot accesses (pipelined, no ordering) ----
__device__ __forceinline__ u64t ldrlx_u64(const u64t* p) {
    u64t r;
    asm volatile("ld.relaxed.gpu.global.u64 %0, [%1];"
                 : "=l"(r) : "l"(p) : "memory");
    return r;
}
__device__ __forceinline__ void strlx_u64(u64t* p, u64t v) {
    asm volatile("st.relaxed.gpu.global.u64 [%0], %1;"
                 :: "l"(p), "l"(v) : "memory");
}
// plain L2 load for pre-computed data (written by an earlier kernel)
__device__ __forceinline__ float ldcg_f32(const float* p) {
    float r;
    asm volatile("ld.global.cg.f32 %0, [%1];" : "=f"(r) : "l"(p));
    return r;
}

// ---------------- init: seed h0 with tag 0, poison other buffer ----------
__global__ void init_kernel(const float* __restrict__ h0) {
    int i = blockIdx.x * blockDim.x + threadIdx.x;
    if (i < DIM) {
        g_ht[0][i] = (u64t)__float_as_uint(h0[i]);      // tag 0 in hi32
        g_ht[1][i] = 0xFFFFFFFF00000000ull;             // poison tag
    }
}

// ---------------- pre-GEMM: pre = x @ W1^T + b1 ----------------
#define BM 128
#define BN 128
#define BK 16

__global__ void __launch_bounds__(256, 2)
gemm_pre_kernel(const float* __restrict__ X, const float* __restrict__ W1,
                const float* __restrict__ b1) {
    __shared__ u64t  Xd[BK * BM];     // 16 KB, duplicated floats
    __shared__ float Ws[BK * BN];     // 8 KB

    const int tid = threadIdx.x;
    const int tx = tid & 15;          // N direction (16)
    const int ty = tid >> 4;          // M direction (16)
    const int m0 = blockIdx.y * BM;
    const int n0 = blockIdx.x * BN;

    u64t acc[8][4];
#pragma unroll
    for (int i = 0; i < 8; i++)
#pragma unroll
        for (int j = 0; j < 4; j++) acc[i][j] = 0ull;

    for (int kt = 0; kt < DIM; kt += BK) {
        __syncthreads();
#pragma unroll
        for (int h = 0; h < 2; h++) {
            int idx = tid + h * 256;
            int k4  = idx & 3;
            int r   = idx >> 2;
            float4 xv = *(const float4*)(X + (size_t)(m0 + r) * DIM + kt + k4 * 4);
            Xd[(k4 * 4 + 0) * BM + r] = pk2(xv.x, xv.x);
            Xd[(k4 * 4 + 1) * BM + r] = pk2(xv.y, xv.y);
            Xd[(k4 * 4 + 2) * BM + r] = pk2(xv.z, xv.z);
            Xd[(k4 * 4 + 3) * BM + r] = pk2(xv.w, xv.w);
            float4 wv = *(const float4*)(W1 + (size_t)(n0 + r) * DIM + kt + k4 * 4);
            Ws[(k4 * 4 + 0) * BN + r] = wv.x;
            Ws[(k4 * 4 + 1) * BN + r] = wv.y;
            Ws[(k4 * 4 + 2) * BN + r] = wv.z;
            Ws[(k4 * 4 + 3) * BN + r] = wv.w;
        }
        __syncthreads();

#pragma unroll
        for (int k = 0; k < BK; k++) {
            const u64t*  Xk = Xd + k * BM;
            const float* Wk = Ws + k * BN;
            u64t a[8];
            {
                ulonglong2 a0 = *(const ulonglong2*)(Xk + ty * 4);
                ulonglong2 a1 = *(const ulonglong2*)(Xk + ty * 4 + 2);
                ulonglong2 a2 = *(const ulonglong2*)(Xk + 64 + ty * 4);
                ulonglong2 a3 = *(const ulonglong2*)(Xk + 64 + ty * 4 + 2);
                a[0] = a0.x; a[1] = a0.y; a[2] = a1.x; a[3] = a1.y;
                a[4] = a2.x; a[5] = a2.y; a[6] = a3.x; a[7] = a3.y;
            }
            u64t bb[4];
            {
                ulonglong2 b0 = *(const ulonglong2*)(Wk + tx * 4);
                ulonglong2 b1v = *(const ulonglong2*)(Wk + 64 + tx * 4);
                bb[0] = b0.x; bb[1] = b0.y; bb[2] = b1v.x; bb[3] = b1v.y;
            }
#pragma unroll
            for (int i = 0; i < 8; i++)
#pragma unroll
                for (int j = 0; j < 4; j++)
                    acc[i][j] = fma2(a[i], bb[j], acc[i][j]);
        }
    }

#pragma unroll
    for (int j = 0; j < 4; j++) {
        int col = n0 + ((j >> 1) * 64) + tx * 4 + (j & 1) * 2;
        u64t bp = pk2(b1[col], b1[col + 1]);
#pragma unroll
        for (int i = 0; i < 8; i++) {
            int row = m0 + ((i >> 2) * 64) + ty * 4 + (i & 3);
            u64t v = add2(acc[i][j], bp);
            *(u64t*)(g_pre + (size_t)row * DIM + col) = v;
        }
    }
}

// ---------------- recurrence: warp-local tagged-slot scan ----------------
// 128 CTAs x 512 threads, 1 CTA/SM, co-resident (128 < 148 SMs).
// Per step t (buffer p = t&1):
//   poll  : warp w polls ONLY its own 128 cols [128w,128w+128): each lane
//           4 slots (stride 32), 4 PARALLEL relaxed u64 loads per round —
//           detection delivers the data (tag+value in one word).
//   stage : lane writes its 4 floats to h_s (warp-local), __syncwarp only.
//   comp  : 32 dependent-pair FMA2s from smem broadcast, W2 in registers.
//   reduce: shfl16 + part[] + ONE __syncthreads + 4 shfl.
//   pub   : lane0 of warp w st.relaxed {t+1 | relu(...)} for row rbase+w.
// Overwrite safety (ping-pong): publishing tag t+1 data-depends on having
// loaded ALL tag-t slots, which data-depended on tag t-1, ... — producers
// can never overwrite a slot a consumer still needs, with no fences.
__global__ void __launch_bounds__(R_THR, 1)
recur_kernel(const float* __restrict__ W2, const float* __restrict__ b2) {
    const int tid  = threadIdx.x;
    const int w    = tid >> 5;
    const int l    = tid & 31;
    const int rowl = l & 15;
    const int half = l >> 4;
    const int rbase = blockIdx.x * 16;
    const int cbase = w * 128 + half * 64;

    u64t wreg[32];
    {
        const ulonglong2* wp =
            (const ulonglong2*)(W2 + (size_t)(rbase + rowl) * DIM + cbase);
#pragma unroll
        for (int i = 0; i < 16; i++) {
            ulonglong2 v = wp[i];
            wreg[2 * i]     = v.x;
            wreg[2 * i + 1] = v.y;
        }
    }
    const float b2r = b2[rbase + w];   // lane 0 of warp w owns row rbase+w

    __shared__ float h_s[DIM];         // staged h_t (each warp its own 128)
    __shared__ float part[16 * 17];

    for (int t = 0; t < T_STEPS; t++) {
        const unsigned tg = (unsigned)t;
        const int p = t & 1;

        float prev = 0.f;
        if (l == 0)    // issued before the poll; latency hidden by it
            prev = ldcg_f32(&g_pre[(size_t)t * DIM + rbase + w]);

        // ---- poll own cols: 4 parallel relaxed loads per round ----
        {
            const u64t* base = g_ht[p] + w * 128 + l;
            u64t v0, v1, v2, v3;
            for (;;) {
                v0 = ldrlx_u64(base);
                v1 = ldrlx_u64(base + 32);
                v2 = ldrlx_u64(base + 64);
                v3 = ldrlx_u64(base + 96);
                if ((unsigned)(v0 >> 32) == tg && (unsigned)(v1 >> 32) == tg &&
                    (unsigned)(v2 >> 32) == tg && (unsigned)(v3 >> 32) == tg)
                    break;
            }
            h_s[w * 128 + l]      = __uint_as_float((unsigned)v0);
            h_s[w * 128 + l + 32] = __uint_as_float((unsigned)v1);
            h_s[w * 128 + l + 64] = __uint_as_float((unsigned)v2);
            h_s[w * 128 + l + 96] = __uint_as_float((unsigned)v3);
        }
        __syncwarp();                  // warp-local stage complete

        // ---- compute: dot from own smem region (broadcast) ----
        const ulonglong2* hp = (const ulonglong2*)(h_s + cbase);
        u64t a0 = 0ull, a1 = 0ull;
#pragma unroll
        for (int i = 0; i < 16; i++) {
            ulonglong2 hv = hp[i];
            a0 = fma2(wreg[2 * i],     hv.x, a0);
            a1 = fma2(wreg[2 * i + 1], hv.y, a1);
        }
        float s = sum2(a0) + sum2(a1);
        s += __shfl_xor_sync(0xffffffffu, s, 16);
        if (half == 0) part[w * 17 + rowl] = s;
        __syncthreads();               // the ONE CTA-wide sync

        float v = (l < 16) ? part[l * 17 + w] : 0.f;
        v += __shfl_xor_sync(0xffffffffu, v, 8);
        v += __shfl_xor_sync(0xffffffffu, v, 4);
        v += __shfl_xor_sync(0xffffffffu, v, 2);
        v += __shfl_xor_sync(0xffffffffu, v, 1);
        if (l == 0) {
            float hnew = fmaxf(v + prev + b2r, 0.f);
            u64t pkd = ((u64t)(tg + 1u) << 32) | (u64t)__float_as_uint(hnew);
            strlx_u64(&g_ht[p ^ 1][rbase + w], pkd);
        }
        // no trailing barrier: next step's poll provides all ordering
    }
}

// ---------------- head: out = h @ Wf^T + bf (1x4) ----------------
__global__ void final_kernel(const float* __restrict__ Wf,
                             const float* __restrict__ bf,
                             float* __restrict__ out) {
    const int w = threadIdx.x >> 5, l = threadIdx.x & 31;
    const u64t* h = g_ht[0];                  // 8192 steps -> parity 0
    float s = 0.f;
    for (int d = l; d < DIM; d += 32)
        s += __uint_as_float((unsigned)h[d]) * Wf[(size_t)w * DIM + d];
    s += __shfl_xor_sync(0xffffffffu, s, 16);
    s += __shfl_xor_sync(0xffffffffu, s, 8);
    s += __shfl_xor_sync(0xffffffffu, s, 4);
    s += __shfl_xor_sync(0xffffffffu, s, 2);
    s += __shfl_xor_sync(0xffffffffu, s, 1);
    if (l == 0) out[w] = s + bf[w];
}

extern "C" void kernel_launch(void* const* d_in, const int* in_sizes, int n_in,
                              void* d_out, int out_size) {
    const float* x  = (const float*)d_in[0];
    const float* h0 = (const float*)d_in[1];
    const float* W1 = (const float*)d_in[2];
    const float* b1 = (const float*)d_in[3];
    const float* W2 = (const float*)d_in[4];
    const float* b2 = (const float*)d_in[5];
    const float* Wf = (const float*)d_in[6];
    const float* bf = (const float*)d_in[7];
    float* out = (float*)d_out;

    init_kernel<<<8, 256>>>(h0);
    dim3 gg(DIM / BN, T_STEPS / BM);          // (16, 64)
    gemm_pre_kernel<<<gg, 256>>>(x, W1, b1);
    recur_kernel<<<R_CTAS, R_THR>>>(W2, b2);
    final_kernel<<<1, 128>>>(Wf, bf, out);
}